// round 2
// baseline (speedup 1.0000x reference)
#include <cuda_runtime.h>
#include <math.h>

#define MAXN 20000
#define MAXE 320000

// ---------------- scratch (static device memory; no allocs) ----------------
__device__ float4 g_ah_src[MAXN * 33];   // per-node vh contribution (src slice), xyz per h
__device__ float4 g_ah_dst[MAXN * 33];   // per-node vh contribution (dst slice)
__device__ float  g_as_src[MAXN * 64];   // node_s @ w1_ws[0:128]
__device__ float  g_as_dst[MAXN * 64];   // node_s @ w1_ws[160:288]
__device__ float  g_s_acc[MAXN * 64];
__device__ float  g_v_acc[MAXN * 12];
__device__ float  g_cnt[MAXN];

// ---------------- shared-memory weight layout (floats) ----------------
#define O_WES   0        // w1_ws rows 128..159   (32*64)
#define O_WVN   2048     // w1_ws rows 288..320   (33*64)
#define O_B1    4160     // 64
#define O_WHE   4224     // w1_wh row 16 (33), padded to 36
#define O_WV1   4260     // 33*4
#define O_WSV1  4392     // 64*4
#define O_BSV1  4648     // 4
#define O_W2H   4652     // 16
#define O_W2S   4668     // 68*64
#define O_B2    9020     // 64
#define O_WV2   9084     // 16
#define O_WSV2  9100     // 256
#define O_BSV2  9356     // 4
#define O_W3H   9360     // 16
#define O_W3S   9376     // 68*64
#define O_B3    13728    // 64
#define O_WV3   13792    // 16
#define O_WSV3  13808    // 256
#define O_BSV3  14064    // 4
#define SMEM_FLOATS 14068
#define SMEM_BYTES (SMEM_FLOATS * 4)

__device__ __forceinline__ float sigmoidf_(float x) {
    return 1.0f / (1.0f + __expf(-x));
}

__device__ __forceinline__ void fma_row(float acc[64], float x, const float* row) {
#pragma unroll
    for (int j = 0; j < 16; j++) {
        float4 w = *(const float4*)(row + j * 4);
        acc[j * 4 + 0] += x * w.x;
        acc[j * 4 + 1] += x * w.y;
        acc[j * 4 + 2] += x * w.z;
        acc[j * 4 + 3] += x * w.w;
    }
}

// GVP layer for layers 2/3 (vi=vo=4, si=so=64)
__device__ __forceinline__ void gvp_small(
    const float* sm, const float sin_[64], const float vin[12],
    float sout[64], float vout[12],
    int o_wh, int o_ws, int o_b, int o_wv, int o_wsv, int o_bsv, bool final_)
{
    // vh[h*3+c] = sum_o vin[o*3+c] * Wh[o][h]
    float vh[12];
#pragma unroll
    for (int h = 0; h < 4; h++) {
        float x = 0.f, y = 0.f, z = 0.f;
#pragma unroll
        for (int o = 0; o < 4; o++) {
            float w = sm[o_wh + o * 4 + h];
            x += vin[o * 3 + 0] * w;
            y += vin[o * 3 + 1] * w;
            z += vin[o * 3 + 2] * w;
        }
        vh[h * 3 + 0] = x; vh[h * 3 + 1] = y; vh[h * 3 + 2] = z;
    }
    float vn2[4];
#pragma unroll
    for (int h = 0; h < 4; h++) {
        float ss = vh[h*3]*vh[h*3] + vh[h*3+1]*vh[h*3+1] + vh[h*3+2]*vh[h*3+2];
        vn2[h] = sqrtf(fmaxf(ss, 1e-8f));
    }
    // vo2[o*3+c] = sum_h vh[h*3+c] * Wv[h][o]
    float vo2[12];
#pragma unroll
    for (int o = 0; o < 4; o++) {
        float x = 0.f, y = 0.f, z = 0.f;
#pragma unroll
        for (int h = 0; h < 4; h++) {
            float w = sm[o_wv + h * 4 + o];
            x += vh[h * 3 + 0] * w;
            y += vh[h * 3 + 1] * w;
            z += vh[h * 3 + 2] * w;
        }
        vo2[o * 3 + 0] = x; vo2[o * 3 + 1] = y; vo2[o * 3 + 2] = z;
    }
    // sout = [sin, vn2] @ Ws + b
#pragma unroll
    for (int j = 0; j < 16; j++) {
        float4 b = *(const float4*)(sm + o_b + j * 4);
        sout[j * 4 + 0] = b.x; sout[j * 4 + 1] = b.y;
        sout[j * 4 + 2] = b.z; sout[j * 4 + 3] = b.w;
    }
#pragma unroll
    for (int k = 0; k < 64; k++) fma_row(sout, sin_[k], sm + o_ws + k * 64);
#pragma unroll
    for (int k = 0; k < 4; k++) fma_row(sout, vn2[k], sm + o_ws + (64 + k) * 64);
    // gate
    float g0, g1, g2, g3;
    {
        float4 b = *(const float4*)(sm + o_bsv);
        g0 = b.x; g1 = b.y; g2 = b.z; g3 = b.w;
    }
#pragma unroll
    for (int k = 0; k < 64; k++) {
        float t = final_ ? sout[k] : sigmoidf_(sout[k]);
        float4 w = *(const float4*)(sm + o_wsv + k * 4);
        g0 += t * w.x; g1 += t * w.y; g2 += t * w.z; g3 += t * w.w;
    }
    float gg0 = sigmoidf_(g0), gg1 = sigmoidf_(g1), gg2 = sigmoidf_(g2), gg3 = sigmoidf_(g3);
#pragma unroll
    for (int c = 0; c < 3; c++) {
        vout[0 * 3 + c] = vo2[0 * 3 + c] * gg0;
        vout[1 * 3 + c] = vo2[1 * 3 + c] * gg1;
        vout[2 * 3 + c] = vo2[2 * 3 + c] * gg2;
        vout[3 * 3 + c] = vo2[3 * 3 + c] * gg3;
    }
    if (!final_) {
#pragma unroll
        for (int k = 0; k < 64; k++) sout[k] = fmaxf(sout[k], 0.f);
    }
}

__device__ __forceinline__ void smcopy(float* d, const float* s, int n) {
    for (int i = threadIdx.x; i < n; i += blockDim.x) d[i] = s[i];
}

// -------- precompute: as_src / as_dst (node_s @ W slices) --------
__global__ void precomp_s_kernel(const float* __restrict__ node_s,
                                 const float* __restrict__ w1_ws)
{
    __shared__ float xs[128];
    int n = blockIdx.x;
    int tid = threadIdx.x;
    xs[tid] = node_s[n * 128 + tid];
    __syncthreads();
    int j = tid & 63;
    const float* W = w1_ws + ((tid >= 64) ? 160 * 64 : 0) + j;
    float acc = 0.f;
#pragma unroll 16
    for (int k = 0; k < 128; k++) acc += xs[k] * W[k * 64];
    if (tid < 64) g_as_src[n * 64 + j] = acc;
    else          g_as_dst[n * 64 + j] = acc;
}

// -------- precompute: ah_src / ah_dst (node_v^T @ Wh slices) --------
__global__ void precomp_v_kernel(const float* __restrict__ node_v,
                                 const float* __restrict__ w1_wh, int N)
{
    int t = blockIdx.x * blockDim.x + threadIdx.x;
    int total = N * 66;
    if (t >= total) return;
    int n = t / 66;
    int r = t - n * 66;
    int h = r % 33;
    bool is_src = (r < 33);
    int base = is_src ? 0 : 17;
    const float* v = node_v + n * 48;
    float x = 0.f, y = 0.f, z = 0.f;
#pragma unroll
    for (int k = 0; k < 16; k++) {
        float w = w1_wh[(base + k) * 33 + h];
        x += v[k * 3 + 0] * w;
        y += v[k * 3 + 1] * w;
        z += v[k * 3 + 2] * w;
    }
    float4 o = make_float4(x, y, z, 0.f);
    if (is_src) g_ah_src[n * 33 + h] = o;
    else        g_ah_dst[n * 33 + h] = o;
}

// -------- main per-edge kernel --------
__global__ void __launch_bounds__(128) edge_kernel(
    const int* __restrict__ ei,
    const float* __restrict__ edge_s,
    const float* __restrict__ edge_v,
    const float* __restrict__ w1_wh, const float* __restrict__ w1_ws,
    const float* __restrict__ w1_wsb, const float* __restrict__ w1_wv,
    const float* __restrict__ w1_wsv, const float* __restrict__ w1_wsvb,
    const float* __restrict__ w2_wh, const float* __restrict__ w2_ws,
    const float* __restrict__ w2_wsb, const float* __restrict__ w2_wv,
    const float* __restrict__ w2_wsv, const float* __restrict__ w2_wsvb,
    const float* __restrict__ w3_wh, const float* __restrict__ w3_ws,
    const float* __restrict__ w3_wsb, const float* __restrict__ w3_wv,
    const float* __restrict__ w3_wsv, const float* __restrict__ w3_wsvb,
    int E)
{
    extern __shared__ float sm[];
    smcopy(sm + O_WES,  w1_ws + 128 * 64, 32 * 64);
    smcopy(sm + O_WVN,  w1_ws + 288 * 64, 33 * 64);
    smcopy(sm + O_B1,   w1_wsb, 64);
    smcopy(sm + O_WHE,  w1_wh + 16 * 33, 33);
    smcopy(sm + O_WV1,  w1_wv, 132);
    smcopy(sm + O_WSV1, w1_wsv, 256);
    smcopy(sm + O_BSV1, w1_wsvb, 4);
    smcopy(sm + O_W2H,  w2_wh, 16);
    smcopy(sm + O_W2S,  w2_ws, 68 * 64);
    smcopy(sm + O_B2,   w2_wsb, 64);
    smcopy(sm + O_WV2,  w2_wv, 16);
    smcopy(sm + O_WSV2, w2_wsv, 256);
    smcopy(sm + O_BSV2, w2_wsvb, 4);
    smcopy(sm + O_W3H,  w3_wh, 16);
    smcopy(sm + O_W3S,  w3_ws, 68 * 64);
    smcopy(sm + O_B3,   w3_wsb, 64);
    smcopy(sm + O_WV3,  w3_wv, 16);
    smcopy(sm + O_WSV3, w3_wsv, 256);
    smcopy(sm + O_BSV3, w3_wsvb, 4);
    __syncthreads();

    for (int e = blockIdx.x * blockDim.x + threadIdx.x; e < E;
         e += gridDim.x * blockDim.x) {
        int src = ei[e];
        int dst = ei[e + E];
        float ev0 = edge_v[e * 3 + 0];
        float ev1 = edge_v[e * 3 + 1];
        float ev2 = edge_v[e * 3 + 2];

        // ---- layer 1 vector path: vh = ah_src[src] + ah_dst[dst] + ev (x) whe
        float vn[33];
        float vo1[12];
#pragma unroll
        for (int i = 0; i < 12; i++) vo1[i] = 0.f;
        const float4* A = g_ah_src + src * 33;
        const float4* B = g_ah_dst + dst * 33;
#pragma unroll
        for (int h = 0; h < 33; h++) {
            float4 a = A[h];
            float4 b = B[h];
            float w = sm[O_WHE + h];
            float x = a.x + b.x + ev0 * w;
            float y = a.y + b.y + ev1 * w;
            float z = a.z + b.z + ev2 * w;
            vn[h] = sqrtf(fmaxf(x * x + y * y + z * z, 1e-8f));
            float4 wv = *(const float4*)(sm + O_WV1 + h * 4);
            vo1[0] += wv.x * x; vo1[1]  += wv.x * y; vo1[2]  += wv.x * z;
            vo1[3] += wv.y * x; vo1[4]  += wv.y * y; vo1[5]  += wv.y * z;
            vo1[6] += wv.z * x; vo1[7]  += wv.z * y; vo1[8]  += wv.z * z;
            vo1[9] += wv.w * x; vo1[10] += wv.w * y; vo1[11] += wv.w * z;
        }

        // ---- layer 1 scalar path
        float s1[64];
        {
            const float4* As = (const float4*)(g_as_src + src * 64);
            const float4* Bs = (const float4*)(g_as_dst + dst * 64);
#pragma unroll
            for (int j = 0; j < 16; j++) {
                float4 a = As[j];
                float4 b = Bs[j];
                float4 c = *(const float4*)(sm + O_B1 + j * 4);
                s1[j * 4 + 0] = a.x + b.x + c.x;
                s1[j * 4 + 1] = a.y + b.y + c.y;
                s1[j * 4 + 2] = a.z + b.z + c.z;
                s1[j * 4 + 3] = a.w + b.w + c.w;
            }
            const float4* ES = (const float4*)(edge_s + (size_t)e * 32);
#pragma unroll
            for (int k4 = 0; k4 < 8; k4++) {
                float4 es = ES[k4];
                fma_row(s1, es.x, sm + O_WES + (k4 * 4 + 0) * 64);
                fma_row(s1, es.y, sm + O_WES + (k4 * 4 + 1) * 64);
                fma_row(s1, es.z, sm + O_WES + (k4 * 4 + 2) * 64);
                fma_row(s1, es.w, sm + O_WES + (k4 * 4 + 3) * 64);
            }
#pragma unroll
            for (int k = 0; k < 33; k++) fma_row(s1, vn[k], sm + O_WVN + k * 64);
        }
        // gate 1
        float v1[12];
        {
            float g0, g1, g2, g3;
            float4 b = *(const float4*)(sm + O_BSV1);
            g0 = b.x; g1 = b.y; g2 = b.z; g3 = b.w;
#pragma unroll
            for (int k = 0; k < 64; k++) {
                float t = sigmoidf_(s1[k]);
                float4 w = *(const float4*)(sm + O_WSV1 + k * 4);
                g0 += t * w.x; g1 += t * w.y; g2 += t * w.z; g3 += t * w.w;
            }
            float gg0 = sigmoidf_(g0), gg1 = sigmoidf_(g1);
            float gg2 = sigmoidf_(g2), gg3 = sigmoidf_(g3);
#pragma unroll
            for (int c = 0; c < 3; c++) {
                v1[0 * 3 + c] = vo1[0 * 3 + c] * gg0;
                v1[1 * 3 + c] = vo1[1 * 3 + c] * gg1;
                v1[2 * 3 + c] = vo1[2 * 3 + c] * gg2;
                v1[3 * 3 + c] = vo1[3 * 3 + c] * gg3;
            }
#pragma unroll
            for (int k = 0; k < 64; k++) s1[k] = fmaxf(s1[k], 0.f);
        }

        // ---- layers 2 and 3
        float s2[64], v2[12];
        gvp_small(sm, s1, v1, s2, v2, O_W2H, O_W2S, O_B2, O_WV2, O_WSV2, O_BSV2, false);
        float s3[64], v3[12];
        gvp_small(sm, s2, v2, s3, v3, O_W3H, O_W3S, O_B3, O_WV3, O_WSV3, O_BSV3, true);

        // ---- scatter-accumulate at dst
        float* sa = g_s_acc + (size_t)dst * 64;
#pragma unroll
        for (int j = 0; j < 64; j++) atomicAdd(sa + j, s3[j]);
        float* va = g_v_acc + (size_t)dst * 12;
#pragma unroll
        for (int j = 0; j < 12; j++) atomicAdd(va + j, v3[j]);
        atomicAdd(g_cnt + dst, 1.0f);
    }
}

// -------- finalize: mean + masked postprocess --------
// mask read as int32 words: correct for both int32 {0,1} and float32 {0.0,1.0}
// encodings of the original bool array (0x3f800000 != 0).
__global__ void finalize_kernel(const int* __restrict__ mask,
                                float* __restrict__ out, int N)
{
    int idx = blockIdx.x * blockDim.x + threadIdx.x;
    int total = N * 64 + N * 4;
    if (idx >= total) return;
    if (idx < N * 64) {
        int n = idx >> 6;
        int j = idx & 63;
        float denom = fmaxf(g_cnt[n], 1.0f);
        float s = g_s_acc[idx] / denom;
        float m = (mask[n] != 0) ? 1.0f : 0.0f;
        float val;
        if (j < 7)       val = cosf(s);
        else if (j < 14) val = sinf(s);
        else             val = expf(s);
        out[idx] = val * m;
    } else {
        int k = idx - N * 64;
        int n = k >> 2;
        int o = k & 3;
        float denom = fmaxf(g_cnt[n], 1.0f);
        float x = g_v_acc[n * 12 + o * 3 + 0] / denom;
        float y = g_v_acc[n * 12 + o * 3 + 1] / denom;
        float z = g_v_acc[n * 12 + o * 3 + 2] / denom;
        float mag = sqrtf(x * x + y * y + z * z);
        float m = (mask[n] != 0) ? 1.0f : 0.0f;
        float sc = m / (mag + 1e-8f);
        float* vout = out + N * 64 + n * 12 + o * 3;
        vout[0] = x * sc;
        vout[1] = y * sc;
        vout[2] = z * sc;
    }
}

extern "C" void kernel_launch(void* const* d_in, const int* in_sizes, int n_in,
                              void* d_out, int out_size)
{
    const float* node_s   = (const float*)d_in[0];
    const float* node_v   = (const float*)d_in[1];
    const int*   ei       = (const int*)d_in[2];
    const float* edge_s   = (const float*)d_in[3];
    const float* edge_v   = (const float*)d_in[4];
    const int*   mask     = (const int*)d_in[5];
    const float* w1_wh  = (const float*)d_in[6];
    const float* w1_ws  = (const float*)d_in[7];
    const float* w1_wsb = (const float*)d_in[8];
    const float* w1_wv  = (const float*)d_in[9];
    const float* w1_wsv = (const float*)d_in[10];
    const float* w1_wsvb= (const float*)d_in[11];
    const float* w2_wh  = (const float*)d_in[12];
    const float* w2_ws  = (const float*)d_in[13];
    const float* w2_wsb = (const float*)d_in[14];
    const float* w2_wv  = (const float*)d_in[15];
    const float* w2_wsv = (const float*)d_in[16];
    const float* w2_wsvb= (const float*)d_in[17];
    const float* w3_wh  = (const float*)d_in[18];
    const float* w3_ws  = (const float*)d_in[19];
    const float* w3_wsb = (const float*)d_in[20];
    const float* w3_wv  = (const float*)d_in[21];
    const float* w3_wsv = (const float*)d_in[22];
    const float* w3_wsvb= (const float*)d_in[23];

    int N = in_sizes[0] / 128;
    int E = in_sizes[3] / 32;
    float* out = (float*)d_out;

    void* p;
    cudaGetSymbolAddress(&p, g_s_acc);
    cudaMemsetAsync(p, 0, (size_t)N * 64 * sizeof(float));
    cudaGetSymbolAddress(&p, g_v_acc);
    cudaMemsetAsync(p, 0, (size_t)N * 12 * sizeof(float));
    cudaGetSymbolAddress(&p, g_cnt);
    cudaMemsetAsync(p, 0, (size_t)N * sizeof(float));

    precomp_s_kernel<<<N, 128>>>(node_s, w1_ws);
    precomp_v_kernel<<<(N * 66 + 127) / 128, 128>>>(node_v, w1_wh, N);

    cudaFuncSetAttribute(edge_kernel,
                         cudaFuncAttributeMaxDynamicSharedMemorySize, SMEM_BYTES);
    int grid = 444;
    edge_kernel<<<grid, 128, SMEM_BYTES>>>(
        ei, edge_s, edge_v,
        w1_wh, w1_ws, w1_wsb, w1_wv, w1_wsv, w1_wsvb,
        w2_wh, w2_ws, w2_wsb, w2_wv, w2_wsv, w2_wsvb,
        w3_wh, w3_ws, w3_wsb, w3_wv, w3_wsv, w3_wsvb,
        E);

    finalize_kernel<<<(N * 68 + 255) / 256, 256>>>(mask, out, N);
}

// round 3
// speedup vs baseline: 1.3095x; 1.3095x over previous
#include <cuda_runtime.h>
#include <math.h>
#include <stdint.h>

#define MAXN 20000

// ---------------- scratch (static device memory; no allocs) ----------------
__device__ float4 g_ah_src[MAXN * 33];
__device__ float4 g_ah_dst[MAXN * 33];
__device__ float  g_as_src[MAXN * 64];
__device__ float  g_as_dst[MAXN * 64];
__device__ float  g_s_acc[MAXN * 64];
__device__ float  g_v_acc[MAXN * 12];
__device__ float  g_cnt[MAXN];

// ---------------- shared-memory weight layout (float indices) ----------------
// Big 64-wide matrices are stored padded: row stride 72, halves at +0 / +36.
#define O_WES   0                      // 32 rows * 72
#define O_WVN   (O_WES + 32*72)        // 33 rows * 72
#define O_B1    (O_WVN + 33*72)        // 64
#define O_WHE   (O_B1 + 64)            // 33 (+3 pad)
#define O_WV1   (O_WHE + 36)           // 33*4
#define O_WSV1  (O_WV1 + 132)          // 64*4
#define O_BSV1  (O_WSV1 + 256)         // 4
#define O_W2H   (O_BSV1 + 4)           // 16
#define O_W2S   (O_W2H + 16)           // 68 rows * 72
#define O_B2    (O_W2S + 68*72)        // 64
#define O_WV2   (O_B2 + 64)            // 16
#define O_WSV2  (O_WV2 + 16)           // 256
#define O_BSV2  (O_WSV2 + 256)         // 4
#define O_W3H   (O_BSV2 + 4)           // 16
#define O_W3S   (O_W3H + 16)           // 68 rows * 72
#define O_B3    (O_W3S + 68*72)        // 64
#define O_WV3   (O_B3 + 64)            // 16
#define O_WSV3  (O_WV3 + 16)           // 256
#define O_BSV3  (O_WSV3 + 256)         // 4
#define SMEM_FLOATS (O_BSV3 + 4)
#define SMEM_BYTES (SMEM_FLOATS * 4)

typedef unsigned long long ull;

__device__ __forceinline__ float sigmoidf_(float x) {
    return 1.0f / (1.0f + __expf(-x));
}

__device__ __forceinline__ ull pack2(float lo, float hi) {
    ull r;
    asm("mov.b64 %0, {%1, %2};" : "=l"(r) : "f"(lo), "f"(hi));
    return r;
}
__device__ __forceinline__ void unpack2(float& lo, float& hi, ull a) {
    asm("mov.b64 {%0, %1}, %2;" : "=f"(lo), "=f"(hi) : "l"(a));
}

// acc[16] packed f32x2 covering 32 floats; row points at this lane's 32-wide half
__device__ __forceinline__ void fma_row32(ull acc[16], float x, const float* row) {
    ull xx = pack2(x, x);
    const ulonglong2* r2 = (const ulonglong2*)row;
#pragma unroll
    for (int j = 0; j < 8; j++) {
        ulonglong2 w = r2[j];
        asm("fma.rn.f32x2 %0, %1, %2, %0;" : "+l"(acc[2*j])   : "l"(xx), "l"(w.x));
        asm("fma.rn.f32x2 %0, %1, %2, %0;" : "+l"(acc[2*j+1]) : "l"(xx), "l"(w.y));
    }
}

// ---------------- GVP layer for layers 2/3 (64 scalars split over lane pair) ----------------
__device__ __forceinline__ void gvp64(
    int p, const float* sm, const float sf_in[32], const float vin[12],
    float sf_out[32], float vout[12],
    int o_wh, int o_ws, int o_b, int o_wv, int o_wsv, int o_bsv, bool final_)
{
    // vector path (duplicated in both lanes of the pair)
    float vh[12];
#pragma unroll
    for (int h = 0; h < 4; h++) {
        float x = 0.f, y = 0.f, z = 0.f;
#pragma unroll
        for (int o = 0; o < 4; o++) {
            float w = sm[o_wh + o * 4 + h];
            x += vin[o*3+0] * w; y += vin[o*3+1] * w; z += vin[o*3+2] * w;
        }
        vh[h*3+0] = x; vh[h*3+1] = y; vh[h*3+2] = z;
    }
    float vn2[4];
#pragma unroll
    for (int h = 0; h < 4; h++)
        vn2[h] = sqrtf(fmaxf(vh[h*3]*vh[h*3] + vh[h*3+1]*vh[h*3+1] + vh[h*3+2]*vh[h*3+2], 1e-8f));
    float vo2[12];
#pragma unroll
    for (int o = 0; o < 4; o++) {
        float x = 0.f, y = 0.f, z = 0.f;
#pragma unroll
        for (int h = 0; h < 4; h++) {
            float w = sm[o_wv + h * 4 + o];
            x += vh[h*3+0] * w; y += vh[h*3+1] * w; z += vh[h*3+2] * w;
        }
        vo2[o*3+0] = x; vo2[o*3+1] = y; vo2[o*3+2] = z;
    }
    // scalar path: acc over this lane's 32 outputs
    ull acc[16];
    {
        const float4* B = (const float4*)(sm + o_b + 32 * p);
#pragma unroll
        for (int j = 0; j < 8; j++) {
            float4 b = B[j];
            acc[2*j]   = pack2(b.x, b.y);
            acc[2*j+1] = pack2(b.z, b.w);
        }
    }
    const float* W = sm + o_ws;
    int half = 36 * p;
#pragma unroll
    for (int r = 0; r < 32; r++) {
        float mine  = sf_in[r];
        float other = __shfl_xor_sync(0xffffffffu, mine, 1);
        float klo = p ? other : mine;   // global row r
        float khi = p ? mine  : other;  // global row 32+r
        fma_row32(acc, klo, W + r * 72 + half);
        fma_row32(acc, khi, W + (32 + r) * 72 + half);
    }
#pragma unroll
    for (int h = 0; h < 4; h++)
        fma_row32(acc, vn2[h], W + (64 + h) * 72 + half);
#pragma unroll
    for (int j = 0; j < 16; j++) unpack2(sf_out[2*j], sf_out[2*j+1], acc[j]);

    // gate: partial over own 32, exchange, bias once
    float p0 = 0.f, p1 = 0.f, p2 = 0.f, p3 = 0.f;
#pragma unroll
    for (int r = 0; r < 32; r++) {
        float t = final_ ? sf_out[r] : sigmoidf_(sf_out[r]);
        float4 w = *(const float4*)(sm + o_wsv + (32 * p + r) * 4);
        p0 += t * w.x; p1 += t * w.y; p2 += t * w.z; p3 += t * w.w;
    }
    float g0 = sm[o_bsv+0] + p0 + __shfl_xor_sync(0xffffffffu, p0, 1);
    float g1 = sm[o_bsv+1] + p1 + __shfl_xor_sync(0xffffffffu, p1, 1);
    float g2 = sm[o_bsv+2] + p2 + __shfl_xor_sync(0xffffffffu, p2, 1);
    float g3 = sm[o_bsv+3] + p3 + __shfl_xor_sync(0xffffffffu, p3, 1);
    g0 = sigmoidf_(g0); g1 = sigmoidf_(g1); g2 = sigmoidf_(g2); g3 = sigmoidf_(g3);
#pragma unroll
    for (int c = 0; c < 3; c++) {
        vout[0*3+c] = vo2[0*3+c] * g0;
        vout[1*3+c] = vo2[1*3+c] * g1;
        vout[2*3+c] = vo2[2*3+c] * g2;
        vout[3*3+c] = vo2[3*3+c] * g3;
    }
    if (!final_) {
#pragma unroll
        for (int r = 0; r < 32; r++) sf_out[r] = fmaxf(sf_out[r], 0.f);
    }
}

__device__ __forceinline__ void smcopy(float* d, const float* s, int n) {
    for (int i = threadIdx.x; i < n; i += blockDim.x) d[i] = s[i];
}
// copy a [K,64] matrix into padded rows of 72 with halves at +0/+36
__device__ __forceinline__ void smcopy_pad(float* d, const float* s, int K) {
    for (int i = threadIdx.x; i < K * 64; i += blockDim.x) {
        int k = i >> 6, c = i & 63;
        d[k * 72 + c + (c >= 32 ? 4 : 0)] = s[i];
    }
}

// -------- precompute: as_src / as_dst --------
__global__ void precomp_s_kernel(const float* __restrict__ node_s,
                                 const float* __restrict__ w1_ws)
{
    __shared__ float xs[128];
    int n = blockIdx.x;
    int tid = threadIdx.x;
    xs[tid] = node_s[n * 128 + tid];
    __syncthreads();
    int j = tid & 63;
    const float* W = w1_ws + ((tid >= 64) ? 160 * 64 : 0) + j;
    float acc = 0.f;
#pragma unroll 16
    for (int k = 0; k < 128; k++) acc += xs[k] * W[k * 64];
    if (tid < 64) g_as_src[n * 64 + j] = acc;
    else          g_as_dst[n * 64 + j] = acc;
}

// -------- precompute: ah_src / ah_dst --------
__global__ void precomp_v_kernel(const float* __restrict__ node_v,
                                 const float* __restrict__ w1_wh, int N)
{
    int t = blockIdx.x * blockDim.x + threadIdx.x;
    int total = N * 66;
    if (t >= total) return;
    int n = t / 66;
    int r = t - n * 66;
    int h = r % 33;
    bool is_src = (r < 33);
    int base = is_src ? 0 : 17;
    const float* v = node_v + n * 48;
    float x = 0.f, y = 0.f, z = 0.f;
#pragma unroll
    for (int k = 0; k < 16; k++) {
        float w = w1_wh[(base + k) * 33 + h];
        x += v[k*3+0] * w; y += v[k*3+1] * w; z += v[k*3+2] * w;
    }
    float4 o = make_float4(x, y, z, 0.f);
    if (is_src) g_ah_src[n * 33 + h] = o;
    else        g_ah_dst[n * 33 + h] = o;
}

// -------- main per-edge kernel: 2 lanes per edge --------
__global__ void __launch_bounds__(128, 3) edge_kernel(
    const int* __restrict__ ei,
    const float* __restrict__ edge_s,
    const float* __restrict__ edge_v,
    const float* __restrict__ w1_wh, const float* __restrict__ w1_ws,
    const float* __restrict__ w1_wsb, const float* __restrict__ w1_wv,
    const float* __restrict__ w1_wsv, const float* __restrict__ w1_wsvb,
    const float* __restrict__ w2_wh, const float* __restrict__ w2_ws,
    const float* __restrict__ w2_wsb, const float* __restrict__ w2_wv,
    const float* __restrict__ w2_wsv, const float* __restrict__ w2_wsvb,
    const float* __restrict__ w3_wh, const float* __restrict__ w3_ws,
    const float* __restrict__ w3_wsb, const float* __restrict__ w3_wv,
    const float* __restrict__ w3_wsv, const float* __restrict__ w3_wsvb,
    int E)
{
    extern __shared__ float sm[];
    smcopy_pad(sm + O_WES, w1_ws + 128 * 64, 32);
    smcopy_pad(sm + O_WVN, w1_ws + 288 * 64, 33);
    smcopy(sm + O_B1,   w1_wsb, 64);
    smcopy(sm + O_WHE,  w1_wh + 16 * 33, 33);
    smcopy(sm + O_WV1,  w1_wv, 132);
    smcopy(sm + O_WSV1, w1_wsv, 256);
    smcopy(sm + O_BSV1, w1_wsvb, 4);
    smcopy(sm + O_W2H,  w2_wh, 16);
    smcopy_pad(sm + O_W2S, w2_ws, 68);
    smcopy(sm + O_B2,   w2_wsb, 64);
    smcopy(sm + O_WV2,  w2_wv, 16);
    smcopy(sm + O_WSV2, w2_wsv, 256);
    smcopy(sm + O_BSV2, w2_wsvb, 4);
    smcopy(sm + O_W3H,  w3_wh, 16);
    smcopy_pad(sm + O_W3S, w3_ws, 68);
    smcopy(sm + O_B3,   w3_wsb, 64);
    smcopy(sm + O_WV3,  w3_wv, 16);
    smcopy(sm + O_WSV3, w3_wsv, 256);
    smcopy(sm + O_BSV3, w3_wsvb, 4);
    __syncthreads();

    const int p = threadIdx.x & 1;
    const int half = 36 * p;
    const int pps = gridDim.x * (blockDim.x >> 1);
    const int base = blockIdx.x * (blockDim.x >> 1) + (threadIdx.x >> 1);
    const int iters = (E + pps - 1) / pps;

    for (int it = 0; it < iters; it++) {
        int P = base + it * pps;
        bool valid = P < E;
        int e = valid ? P : 0;
        int src = ei[e];
        int dst = ei[e + E];
        float ev0 = edge_v[e*3+0], ev1 = edge_v[e*3+1], ev2 = edge_v[e*3+2];

        // ---- layer 1 scalar acc init: bias + as_src + as_dst (lane's half)
        ull acc[16];
        {
            const float4* As = (const float4*)(g_as_src + src * 64 + 32 * p);
            const float4* Bs = (const float4*)(g_as_dst + dst * 64 + 32 * p);
            const float4* Cb = (const float4*)(sm + O_B1 + 32 * p);
#pragma unroll
            for (int j = 0; j < 8; j++) {
                float4 a = As[j], b = Bs[j], c = Cb[j];
                acc[2*j]   = pack2(a.x + b.x + c.x, a.y + b.y + c.y);
                acc[2*j+1] = pack2(a.z + b.z + c.z, a.w + b.w + c.w);
            }
        }
        // ---- edge_s rows
        {
            const float4* ES = (const float4*)(edge_s + (size_t)e * 32);
#pragma unroll
            for (int k4 = 0; k4 < 8; k4++) {
                float4 es = ES[k4];
                fma_row32(acc, es.x, sm + O_WES + (k4*4+0) * 72 + half);
                fma_row32(acc, es.y, sm + O_WES + (k4*4+1) * 72 + half);
                fma_row32(acc, es.z, sm + O_WES + (k4*4+2) * 72 + half);
                fma_row32(acc, es.w, sm + O_WES + (k4*4+3) * 72 + half);
            }
        }
        // ---- vector path fused with vn rows (duplicated across the pair)
        float vo1[12];
#pragma unroll
        for (int i = 0; i < 12; i++) vo1[i] = 0.f;
        {
            const float4* A = g_ah_src + src * 33;
            const float4* B = g_ah_dst + dst * 33;
#pragma unroll
            for (int h = 0; h < 33; h++) {
                float4 a = A[h];
                float4 b = B[h];
                float w = sm[O_WHE + h];
                float x = a.x + b.x + ev0 * w;
                float y = a.y + b.y + ev1 * w;
                float z = a.z + b.z + ev2 * w;
                float vn = sqrtf(fmaxf(x*x + y*y + z*z, 1e-8f));
                fma_row32(acc, vn, sm + O_WVN + h * 72 + half);
                float4 wv = *(const float4*)(sm + O_WV1 + h * 4);
                vo1[0] += wv.x * x; vo1[1]  += wv.x * y; vo1[2]  += wv.x * z;
                vo1[3] += wv.y * x; vo1[4]  += wv.y * y; vo1[5]  += wv.y * z;
                vo1[6] += wv.z * x; vo1[7]  += wv.z * y; vo1[8]  += wv.z * z;
                vo1[9] += wv.w * x; vo1[10] += wv.w * y; vo1[11] += wv.w * z;
            }
        }
        float s1f[32];
#pragma unroll
        for (int j = 0; j < 16; j++) unpack2(s1f[2*j], s1f[2*j+1], acc[j]);

        // ---- gate 1
        float v1[12];
        {
            float p0 = 0.f, p1 = 0.f, p2 = 0.f, p3 = 0.f;
#pragma unroll
            for (int r = 0; r < 32; r++) {
                float t = sigmoidf_(s1f[r]);
                float4 w = *(const float4*)(sm + O_WSV1 + (32 * p + r) * 4);
                p0 += t * w.x; p1 += t * w.y; p2 += t * w.z; p3 += t * w.w;
            }
            float g0 = sm[O_BSV1+0] + p0 + __shfl_xor_sync(0xffffffffu, p0, 1);
            float g1 = sm[O_BSV1+1] + p1 + __shfl_xor_sync(0xffffffffu, p1, 1);
            float g2 = sm[O_BSV1+2] + p2 + __shfl_xor_sync(0xffffffffu, p2, 1);
            float g3 = sm[O_BSV1+3] + p3 + __shfl_xor_sync(0xffffffffu, p3, 1);
            g0 = sigmoidf_(g0); g1 = sigmoidf_(g1); g2 = sigmoidf_(g2); g3 = sigmoidf_(g3);
#pragma unroll
            for (int c = 0; c < 3; c++) {
                v1[0*3+c] = vo1[0*3+c] * g0;
                v1[1*3+c] = vo1[1*3+c] * g1;
                v1[2*3+c] = vo1[2*3+c] * g2;
                v1[3*3+c] = vo1[3*3+c] * g3;
            }
#pragma unroll
            for (int r = 0; r < 32; r++) s1f[r] = fmaxf(s1f[r], 0.f);
        }

        // ---- layers 2 and 3
        float s2f[32], v2[12];
        gvp64(p, sm, s1f, v1, s2f, v2, O_W2H, O_W2S, O_B2, O_WV2, O_WSV2, O_BSV2, false);
        float s3f[32], v3[12];
        gvp64(p, sm, s2f, v2, s3f, v3, O_W3H, O_W3S, O_B3, O_WV3, O_WSV3, O_BSV3, true);

        // ---- scatter-accumulate at dst
        if (valid) {
            float* sa = g_s_acc + (size_t)dst * 64 + 32 * p;
#pragma unroll
            for (int j = 0; j < 32; j++) atomicAdd(sa + j, s3f[j]);
            float* va = g_v_acc + (size_t)dst * 12 + 6 * p;
#pragma unroll
            for (int j = 0; j < 6; j++) atomicAdd(va + j, v3[6 * p + j]);
            if (p == 0) atomicAdd(g_cnt + dst, 1.0f);
        }
    }
}

// -------- finalize --------
__global__ void finalize_kernel(const int* __restrict__ mask,
                                float* __restrict__ out, int N)
{
    int idx = blockIdx.x * blockDim.x + threadIdx.x;
    int total = N * 64 + N * 4;
    if (idx >= total) return;
    if (idx < N * 64) {
        int n = idx >> 6;
        int j = idx & 63;
        float denom = fmaxf(g_cnt[n], 1.0f);
        float s = g_s_acc[idx] / denom;
        float m = (mask[n] != 0) ? 1.0f : 0.0f;
        float val;
        if (j < 7)       val = cosf(s);
        else if (j < 14) val = sinf(s);
        else             val = expf(s);
        out[idx] = val * m;
    } else {
        int k = idx - N * 64;
        int n = k >> 2;
        int o = k & 3;
        float denom = fmaxf(g_cnt[n], 1.0f);
        float x = g_v_acc[n*12 + o*3 + 0] / denom;
        float y = g_v_acc[n*12 + o*3 + 1] / denom;
        float z = g_v_acc[n*12 + o*3 + 2] / denom;
        float mag = sqrtf(x*x + y*y + z*z);
        float m = (mask[n] != 0) ? 1.0f : 0.0f;
        float sc = m / (mag + 1e-8f);
        float* vout = out + N * 64 + n * 12 + o * 3;
        vout[0] = x * sc; vout[1] = y * sc; vout[2] = z * sc;
    }
}

extern "C" void kernel_launch(void* const* d_in, const int* in_sizes, int n_in,
                              void* d_out, int out_size)
{
    const float* node_s = (const float*)d_in[0];
    const float* node_v = (const float*)d_in[1];
    const int*   ei     = (const int*)d_in[2];
    const float* edge_s = (const float*)d_in[3];
    const float* edge_v = (const float*)d_in[4];
    const int*   mask   = (const int*)d_in[5];
    const float* w1_wh  = (const float*)d_in[6];
    const float* w1_ws  = (const float*)d_in[7];
    const float* w1_wsb = (const float*)d_in[8];
    const float* w1_wv  = (const float*)d_in[9];
    const float* w1_wsv = (const float*)d_in[10];
    const float* w1_wsvb= (const float*)d_in[11];
    const float* w2_wh  = (const float*)d_in[12];
    const float* w2_ws  = (const float*)d_in[13];
    const float* w2_wsb = (const float*)d_in[14];
    const float* w2_wv  = (const float*)d_in[15];
    const float* w2_wsv = (const float*)d_in[16];
    const float* w2_wsvb= (const float*)d_in[17];
    const float* w3_wh  = (const float*)d_in[18];
    const float* w3_ws  = (const float*)d_in[19];
    const float* w3_wsb = (const float*)d_in[20];
    const float* w3_wv  = (const float*)d_in[21];
    const float* w3_wsv = (const float*)d_in[22];
    const float* w3_wsvb= (const float*)d_in[23];

    int N = in_sizes[0] / 128;
    int E = in_sizes[3] / 32;
    float* out = (float*)d_out;

    void* ptr;
    cudaGetSymbolAddress(&ptr, g_s_acc);
    cudaMemsetAsync(ptr, 0, (size_t)N * 64 * sizeof(float));
    cudaGetSymbolAddress(&ptr, g_v_acc);
    cudaMemsetAsync(ptr, 0, (size_t)N * 12 * sizeof(float));
    cudaGetSymbolAddress(&ptr, g_cnt);
    cudaMemsetAsync(ptr, 0, (size_t)N * sizeof(float));

    precomp_s_kernel<<<N, 128>>>(node_s, w1_ws);
    precomp_v_kernel<<<(N * 66 + 127) / 128, 128>>>(node_v, w1_wh, N);

    cudaFuncSetAttribute(edge_kernel,
                         cudaFuncAttributeMaxDynamicSharedMemorySize, SMEM_BYTES);
    int grid = 444;   // 148 SMs * 3 blocks (smem-limited), single wave
    edge_kernel<<<grid, 128, SMEM_BYTES>>>(
        ei, edge_s, edge_v,
        w1_wh, w1_ws, w1_wsb, w1_wv, w1_wsv, w1_wsvb,
        w2_wh, w2_ws, w2_wsb, w2_wv, w2_wsv, w2_wsvb,
        w3_wh, w3_ws, w3_wsb, w3_wv, w3_wsv, w3_wsvb,
        E);

    finalize_kernel<<<(N * 68 + 255) / 256, 256>>>(mask, out, N);
}

// round 4
// speedup vs baseline: 1.9289x; 1.4730x over previous
#include <cuda_runtime.h>
#include <math.h>
#include <stdint.h>

#define MAXN 20000

// ---------------- scratch (static device memory; no allocs) ----------------
__device__ float4 g_ah_src[MAXN * 34];   // 34 rows/node, row 33 = zero pad
__device__ float4 g_ah_dst[MAXN * 34];
__device__ float  g_as_src[MAXN * 64];
__device__ float  g_as_dst[MAXN * 64];
__device__ float  g_s_acc[MAXN * 64];
__device__ float  g_v_acc[MAXN * 12];
__device__ float  g_cnt[MAXN];

// ---------------- shared-memory weight layout (float indices) ----------------
// 64-wide matrices padded: row stride 72, halves at +0 / +36.
#define O_WES   0                       // 32 rows * 72
#define O_WVN   (O_WES + 32*72)         // 34 rows * 72 (row 33 zero)
#define O_B1    (O_WVN + 34*72)         // 64
#define O_WHE   (O_B1 + 64)             // 36 (33 + zero pad)
#define O_WV1   (O_WHE + 36)            // 136 (33*4 + pad)
#define O_WSV1  (O_WV1 + 136)           // 256
#define O_BSV1  (O_WSV1 + 256)          // 4
#define O_W2H   (O_BSV1 + 4)            // 16
#define O_W2S   (O_W2H + 16)            // 68 rows * 72
#define O_B2    (O_W2S + 68*72)         // 64
#define O_WV2   (O_B2 + 64)             // 16
#define O_WSV2  (O_WV2 + 16)            // 256
#define O_BSV2  (O_WSV2 + 256)          // 4
#define O_W3H   (O_BSV2 + 4)            // 16
#define O_W3S   (O_W3H + 16)            // 68 rows * 72
#define O_B3    (O_W3S + 68*72)         // 64
#define O_WV3   (O_B3 + 64)             // 16
#define O_WSV3  (O_WV3 + 16)            // 256
#define O_BSV3  (O_WSV3 + 256)          // 4
#define SMEM_FLOATS (O_BSV3 + 4)
#define SMEM_BYTES (SMEM_FLOATS * 4)

typedef unsigned long long ull;

__device__ __forceinline__ float fsig(float x) {
    float t;
    asm("ex2.approx.f32 %0, %1;" : "=f"(t) : "f"(x * -1.4426950408889634f));
    float r;
    asm("rcp.approx.f32 %0, %1;" : "=f"(r) : "f"(t + 1.0f));
    return r;
}
__device__ __forceinline__ float fsqrt_(float x) {
    float r;
    asm("sqrt.approx.f32 %0, %1;" : "=f"(r) : "f"(x));
    return r;
}

__device__ __forceinline__ ull pack2(float lo, float hi) {
    ull r;
    asm("mov.b64 %0, {%1, %2};" : "=l"(r) : "f"(lo), "f"(hi));
    return r;
}
__device__ __forceinline__ void unpack2(float& lo, float& hi, ull a) {
    asm("mov.b64 {%0, %1}, %2;" : "=f"(lo), "=f"(hi) : "l"(a));
}

// acc[16] packed f32x2 covering 32 floats; row -> this lane's 32-wide half
__device__ __forceinline__ void fma_row32(ull acc[16], float x, const float* row) {
    ull xx = pack2(x, x);
    const ulonglong2* r2 = (const ulonglong2*)row;
#pragma unroll
    for (int j = 0; j < 8; j++) {
        ulonglong2 w = r2[j];
        asm("fma.rn.f32x2 %0, %1, %2, %0;" : "+l"(acc[2*j])   : "l"(xx), "l"(w.x));
        asm("fma.rn.f32x2 %0, %1, %2, %0;" : "+l"(acc[2*j+1]) : "l"(xx), "l"(w.y));
    }
}

// ---------------- GVP layer for layers 2/3 (64 scalars split over lane pair) ----------------
__device__ __forceinline__ void gvp64(
    int p, const float* sm, const float sf_in[32], const float vin[12],
    float sf_out[32], float vout[12],
    int o_wh, int o_ws, int o_b, int o_wv, int o_wsv, int o_bsv, bool final_)
{
    float vh[12];
#pragma unroll
    for (int h = 0; h < 4; h++) {
        float x = 0.f, y = 0.f, z = 0.f;
#pragma unroll
        for (int o = 0; o < 4; o++) {
            float w = sm[o_wh + o * 4 + h];
            x += vin[o*3+0] * w; y += vin[o*3+1] * w; z += vin[o*3+2] * w;
        }
        vh[h*3+0] = x; vh[h*3+1] = y; vh[h*3+2] = z;
    }
    float vn2[4];
#pragma unroll
    for (int h = 0; h < 4; h++)
        vn2[h] = fsqrt_(fmaxf(vh[h*3]*vh[h*3] + vh[h*3+1]*vh[h*3+1] + vh[h*3+2]*vh[h*3+2], 1e-8f));
    float vo2[12];
#pragma unroll
    for (int o = 0; o < 4; o++) {
        float x = 0.f, y = 0.f, z = 0.f;
#pragma unroll
        for (int h = 0; h < 4; h++) {
            float w = sm[o_wv + h * 4 + o];
            x += vh[h*3+0] * w; y += vh[h*3+1] * w; z += vh[h*3+2] * w;
        }
        vo2[o*3+0] = x; vo2[o*3+1] = y; vo2[o*3+2] = z;
    }
    ull acc[16];
    {
        const float4* B = (const float4*)(sm + o_b + 32 * p);
#pragma unroll
        for (int j = 0; j < 8; j++) {
            float4 b = B[j];
            acc[2*j]   = pack2(b.x, b.y);
            acc[2*j+1] = pack2(b.z, b.w);
        }
    }
    const float* W = sm + o_ws;
    int half = 36 * p;
#pragma unroll
    for (int r = 0; r < 32; r++) {
        float mine  = sf_in[r];
        float other = __shfl_xor_sync(0xffffffffu, mine, 1);
        float klo = p ? other : mine;
        float khi = p ? mine  : other;
        fma_row32(acc, klo, W + r * 72 + half);
        fma_row32(acc, khi, W + (32 + r) * 72 + half);
    }
#pragma unroll
    for (int h = 0; h < 4; h++)
        fma_row32(acc, vn2[h], W + (64 + h) * 72 + half);
#pragma unroll
    for (int j = 0; j < 16; j++) unpack2(sf_out[2*j], sf_out[2*j+1], acc[j]);

    float p0 = 0.f, p1 = 0.f, p2 = 0.f, p3 = 0.f;
#pragma unroll
    for (int r = 0; r < 32; r++) {
        float t = final_ ? sf_out[r] : fsig(sf_out[r]);
        float4 w = *(const float4*)(sm + o_wsv + (32 * p + r) * 4);
        p0 += t * w.x; p1 += t * w.y; p2 += t * w.z; p3 += t * w.w;
    }
    float g0 = sm[o_bsv+0] + p0 + __shfl_xor_sync(0xffffffffu, p0, 1);
    float g1 = sm[o_bsv+1] + p1 + __shfl_xor_sync(0xffffffffu, p1, 1);
    float g2 = sm[o_bsv+2] + p2 + __shfl_xor_sync(0xffffffffu, p2, 1);
    float g3 = sm[o_bsv+3] + p3 + __shfl_xor_sync(0xffffffffu, p3, 1);
    g0 = fsig(g0); g1 = fsig(g1); g2 = fsig(g2); g3 = fsig(g3);
#pragma unroll
    for (int c = 0; c < 3; c++) {
        vout[0*3+c] = vo2[0*3+c] * g0;
        vout[1*3+c] = vo2[1*3+c] * g1;
        vout[2*3+c] = vo2[2*3+c] * g2;
        vout[3*3+c] = vo2[3*3+c] * g3;
    }
    if (!final_) {
#pragma unroll
        for (int r = 0; r < 32; r++) sf_out[r] = fmaxf(sf_out[r], 0.f);
    }
}

__device__ __forceinline__ void smcopy(float* d, const float* s, int n) {
    for (int i = threadIdx.x; i < n; i += blockDim.x) d[i] = s[i];
}
__device__ __forceinline__ void smcopy_pad(float* d, const float* s, int K) {
    for (int i = threadIdx.x; i < K * 64; i += blockDim.x) {
        int k = i >> 6, c = i & 63;
        d[k * 72 + c + (c >= 32 ? 4 : 0)] = s[i];
    }
}

// -------- prep: zero accumulators + per-node precompute (one block per node) --------
__global__ void prep_kernel(const float* __restrict__ node_s,
                            const float* __restrict__ node_v,
                            const float* __restrict__ w1_wh,
                            const float* __restrict__ w1_ws)
{
    __shared__ float xs[128];
    int n = blockIdx.x;
    int tid = threadIdx.x;
    xs[tid] = node_s[n * 128 + tid];
    // zero accumulators for this node
    if (tid < 64) g_s_acc[n * 64 + tid] = 0.f;
    else if (tid < 76) g_v_acc[n * 12 + (tid - 64)] = 0.f;
    else if (tid == 76) g_cnt[n] = 0.f;
    // ah precompute (threads 0..65) + zero pad rows (66,67)
    if (tid < 66) {
        int h = (tid < 33) ? tid : tid - 33;
        bool is_src = (tid < 33);
        int base = is_src ? 0 : 17;
        const float* v = node_v + n * 48;
        float x = 0.f, y = 0.f, z = 0.f;
#pragma unroll
        for (int k = 0; k < 16; k++) {
            float w = w1_wh[(base + k) * 33 + h];
            x += v[k*3+0] * w; y += v[k*3+1] * w; z += v[k*3+2] * w;
        }
        float4 o = make_float4(x, y, z, 0.f);
        if (is_src) g_ah_src[n * 34 + h] = o;
        else        g_ah_dst[n * 34 + h] = o;
    } else if (tid == 66) {
        g_ah_src[n * 34 + 33] = make_float4(0.f, 0.f, 0.f, 0.f);
    } else if (tid == 67) {
        g_ah_dst[n * 34 + 33] = make_float4(0.f, 0.f, 0.f, 0.f);
    }
    __syncthreads();
    int j = tid & 63;
    const float* W = w1_ws + ((tid >= 64) ? 160 * 64 : 0) + j;
    float acc = 0.f;
#pragma unroll 16
    for (int k = 0; k < 128; k++) acc += xs[k] * W[k * 64];
    if (tid < 64) g_as_src[n * 64 + j] = acc;
    else          g_as_dst[n * 64 + j] = acc;
}

// -------- main per-edge kernel: 2 lanes per edge --------
__global__ void __launch_bounds__(128, 3) edge_kernel(
    const int* __restrict__ ei,
    const float* __restrict__ edge_s,
    const float* __restrict__ edge_v,
    const float* __restrict__ w1_wh, const float* __restrict__ w1_ws,
    const float* __restrict__ w1_wsb, const float* __restrict__ w1_wv,
    const float* __restrict__ w1_wsv, const float* __restrict__ w1_wsvb,
    const float* __restrict__ w2_wh, const float* __restrict__ w2_ws,
    const float* __restrict__ w2_wsb, const float* __restrict__ w2_wv,
    const float* __restrict__ w2_wsv, const float* __restrict__ w2_wsvb,
    const float* __restrict__ w3_wh, const float* __restrict__ w3_ws,
    const float* __restrict__ w3_wsb, const float* __restrict__ w3_wv,
    const float* __restrict__ w3_wsv, const float* __restrict__ w3_wsvb,
    int E)
{
    extern __shared__ float sm[];
    smcopy_pad(sm + O_WES, w1_ws + 128 * 64, 32);
    smcopy_pad(sm + O_WVN, w1_ws + 288 * 64, 33);
    smcopy(sm + O_WVN + 33 * 72, (const float*)nullptr, 0); // no-op
    for (int i = threadIdx.x; i < 72; i += blockDim.x) sm[O_WVN + 33 * 72 + i] = 0.f;
    smcopy(sm + O_B1,   w1_wsb, 64);
    smcopy(sm + O_WHE,  w1_wh + 16 * 33, 33);
    for (int i = threadIdx.x + 33; i < 36; i += blockDim.x) sm[O_WHE + i] = 0.f;
    smcopy(sm + O_WV1,  w1_wv, 132);
    for (int i = threadIdx.x + 132; i < 136; i += blockDim.x) sm[O_WV1 + i] = 0.f;
    smcopy(sm + O_WSV1, w1_wsv, 256);
    smcopy(sm + O_BSV1, w1_wsvb, 4);
    smcopy(sm + O_W2H,  w2_wh, 16);
    smcopy_pad(sm + O_W2S, w2_ws, 68);
    smcopy(sm + O_B2,   w2_wsb, 64);
    smcopy(sm + O_WV2,  w2_wv, 16);
    smcopy(sm + O_WSV2, w2_wsv, 256);
    smcopy(sm + O_BSV2, w2_wsvb, 4);
    smcopy(sm + O_W3H,  w3_wh, 16);
    smcopy_pad(sm + O_W3S, w3_ws, 68);
    smcopy(sm + O_B3,   w3_wsb, 64);
    smcopy(sm + O_WV3,  w3_wv, 16);
    smcopy(sm + O_WSV3, w3_wsv, 256);
    smcopy(sm + O_BSV3, w3_wsvb, 4);
    __syncthreads();

    const int p = threadIdx.x & 1;
    const int half = 36 * p;
    const int hs = 17 * p;                 // own h range start
    const int pps = gridDim.x * (blockDim.x >> 1);
    const int base = blockIdx.x * (blockDim.x >> 1) + (threadIdx.x >> 1);
    const int iters = (E + pps - 1) / pps;

    for (int it = 0; it < iters; it++) {
        int P = base + it * pps;
        bool valid = P < E;
        int e = valid ? P : 0;
        int src = ei[e];
        int dst = ei[e + E];
        float ev0 = edge_v[e*3+0], ev1 = edge_v[e*3+1], ev2 = edge_v[e*3+2];

        // ---- layer 1 scalar acc init: bias + as_src + as_dst (lane's half)
        ull acc[16];
        {
            const float4* As = (const float4*)(g_as_src + src * 64 + 32 * p);
            const float4* Bs = (const float4*)(g_as_dst + dst * 64 + 32 * p);
            const float4* Cb = (const float4*)(sm + O_B1 + 32 * p);
#pragma unroll
            for (int j = 0; j < 8; j++) {
                float4 a = As[j], b = Bs[j], c = Cb[j];
                acc[2*j]   = pack2(a.x + b.x + c.x, a.y + b.y + c.y);
                acc[2*j+1] = pack2(a.z + b.z + c.z, a.w + b.w + c.w);
            }
        }
        // ---- edge_s rows
        {
            const float4* ES = (const float4*)(edge_s + (size_t)e * 32);
#pragma unroll
            for (int k4 = 0; k4 < 8; k4++) {
                float4 es = ES[k4];
                fma_row32(acc, es.x, sm + O_WES + (k4*4+0) * 72 + half);
                fma_row32(acc, es.y, sm + O_WES + (k4*4+1) * 72 + half);
                fma_row32(acc, es.z, sm + O_WES + (k4*4+2) * 72 + half);
                fma_row32(acc, es.w, sm + O_WES + (k4*4+3) * 72 + half);
            }
        }
        // ---- layer-1 vector path: each lane handles 17 h's (lane1's last is zero pad)
        float vn_own[17];
        float vo1p[12];
#pragma unroll
        for (int i = 0; i < 12; i++) vo1p[i] = 0.f;
        {
            const float4* A = g_ah_src + src * 34 + hs;
            const float4* B = g_ah_dst + dst * 34 + hs;
#pragma unroll
            for (int k = 0; k < 17; k++) {
                int h = hs + k;
                float4 a = A[k];
                float4 b = B[k];
                float w = sm[O_WHE + h];
                float x = a.x + b.x + ev0 * w;
                float y = a.y + b.y + ev1 * w;
                float z = a.z + b.z + ev2 * w;
                float vn = fsqrt_(fmaxf(x*x + y*y + z*z, 1e-8f));
                vn_own[k] = vn;
                fma_row32(acc, vn, sm + O_WVN + h * 72 + half);
                float4 wv = *(const float4*)(sm + O_WV1 + h * 4);
                vo1p[0] += wv.x * x; vo1p[1]  += wv.x * y; vo1p[2]  += wv.x * z;
                vo1p[3] += wv.y * x; vo1p[4]  += wv.y * y; vo1p[5]  += wv.y * z;
                vo1p[6] += wv.z * x; vo1p[7]  += wv.z * y; vo1p[8]  += wv.z * z;
                vo1p[9] += wv.w * x; vo1p[10] += wv.w * y; vo1p[11] += wv.w * z;
            }
            // partner's vn rows
#pragma unroll
            for (int k = 0; k < 17; k++) {
                float vnp = __shfl_xor_sync(0xffffffffu, vn_own[k], 1);
                int h = p ? k : 17 + k;   // partner owned h (lane0 gets 17+k incl. pad 33)
                fma_row32(acc, vnp, sm + O_WVN + h * 72 + half);
            }
        }
        float vo1[12];
#pragma unroll
        for (int i = 0; i < 12; i++)
            vo1[i] = vo1p[i] + __shfl_xor_sync(0xffffffffu, vo1p[i], 1);

        float s1f[32];
#pragma unroll
        for (int j = 0; j < 16; j++) unpack2(s1f[2*j], s1f[2*j+1], acc[j]);

        // ---- gate 1
        float v1[12];
        {
            float p0 = 0.f, p1 = 0.f, p2 = 0.f, p3 = 0.f;
#pragma unroll
            for (int r = 0; r < 32; r++) {
                float t = fsig(s1f[r]);
                float4 w = *(const float4*)(sm + O_WSV1 + (32 * p + r) * 4);
                p0 += t * w.x; p1 += t * w.y; p2 += t * w.z; p3 += t * w.w;
            }
            float g0 = sm[O_BSV1+0] + p0 + __shfl_xor_sync(0xffffffffu, p0, 1);
            float g1 = sm[O_BSV1+1] + p1 + __shfl_xor_sync(0xffffffffu, p1, 1);
            float g2 = sm[O_BSV1+2] + p2 + __shfl_xor_sync(0xffffffffu, p2, 1);
            float g3 = sm[O_BSV1+3] + p3 + __shfl_xor_sync(0xffffffffu, p3, 1);
            g0 = fsig(g0); g1 = fsig(g1); g2 = fsig(g2); g3 = fsig(g3);
#pragma unroll
            for (int c = 0; c < 3; c++) {
                v1[0*3+c] = vo1[0*3+c] * g0;
                v1[1*3+c] = vo1[1*3+c] * g1;
                v1[2*3+c] = vo1[2*3+c] * g2;
                v1[3*3+c] = vo1[3*3+c] * g3;
            }
#pragma unroll
            for (int r = 0; r < 32; r++) s1f[r] = fmaxf(s1f[r], 0.f);
        }

        // ---- layers 2 and 3
        float s2f[32], v2[12];
        gvp64(p, sm, s1f, v1, s2f, v2, O_W2H, O_W2S, O_B2, O_WV2, O_WSV2, O_BSV2, false);
        float s3f[32], v3[12];
        gvp64(p, sm, s2f, v2, s3f, v3, O_W3H, O_W3S, O_B3, O_WV3, O_WSV3, O_BSV3, true);

        // ---- scatter-accumulate at dst (vectorized reductions)
        if (valid) {
            float* sa = g_s_acc + (size_t)dst * 64 + 32 * p;
#pragma unroll
            for (int j = 0; j < 8; j++) {
                asm volatile("red.global.add.v4.f32 [%0], {%1, %2, %3, %4};"
                    :: "l"(sa + 4*j),
                       "f"(s3f[4*j]), "f"(s3f[4*j+1]), "f"(s3f[4*j+2]), "f"(s3f[4*j+3])
                    : "memory");
            }
            float* va = g_v_acc + (size_t)dst * 12 + 6 * p;
#pragma unroll
            for (int j = 0; j < 3; j++) {
                asm volatile("red.global.add.v2.f32 [%0], {%1, %2};"
                    :: "l"(va + 2*j), "f"(v3[6*p + 2*j]), "f"(v3[6*p + 2*j+1])
                    : "memory");
            }
            if (p == 0) atomicAdd(g_cnt + dst, 1.0f);
        }
    }
}

// -------- finalize (split in two so -s 5 lands on edge_kernel) --------
__global__ void finalize_s_kernel(const int* __restrict__ mask,
                                  float* __restrict__ out, int N)
{
    int idx = blockIdx.x * blockDim.x + threadIdx.x;
    if (idx >= N * 64) return;
    int n = idx >> 6;
    int j = idx & 63;
    float denom = fmaxf(g_cnt[n], 1.0f);
    float s = g_s_acc[idx] / denom;
    float m = (mask[n] != 0) ? 1.0f : 0.0f;
    float val;
    if (j < 7)       val = cosf(s);
    else if (j < 14) val = sinf(s);
    else             val = expf(s);
    out[idx] = val * m;
}

__global__ void finalize_v_kernel(const int* __restrict__ mask,
                                  float* __restrict__ out, int N)
{
    int k = blockIdx.x * blockDim.x + threadIdx.x;
    if (k >= N * 4) return;
    int n = k >> 2;
    int o = k & 3;
    float denom = fmaxf(g_cnt[n], 1.0f);
    float x = g_v_acc[n*12 + o*3 + 0] / denom;
    float y = g_v_acc[n*12 + o*3 + 1] / denom;
    float z = g_v_acc[n*12 + o*3 + 2] / denom;
    float mag = sqrtf(x*x + y*y + z*z);
    float m = (mask[n] != 0) ? 1.0f : 0.0f;
    float sc = m / (mag + 1e-8f);
    float* vout = out + N * 64 + n * 12 + o * 3;
    vout[0] = x * sc; vout[1] = y * sc; vout[2] = z * sc;
}

extern "C" void kernel_launch(void* const* d_in, const int* in_sizes, int n_in,
                              void* d_out, int out_size)
{
    const float* node_s = (const float*)d_in[0];
    const float* node_v = (const float*)d_in[1];
    const int*   ei     = (const int*)d_in[2];
    const float* edge_s = (const float*)d_in[3];
    const float* edge_v = (const float*)d_in[4];
    const int*   mask   = (const int*)d_in[5];
    const float* w1_wh  = (const float*)d_in[6];
    const float* w1_ws  = (const float*)d_in[7];
    const float* w1_wsb = (const float*)d_in[8];
    const float* w1_wv  = (const float*)d_in[9];
    const float* w1_wsv = (const float*)d_in[10];
    const float* w1_wsvb= (const float*)d_in[11];
    const float* w2_wh  = (const float*)d_in[12];
    const float* w2_ws  = (const float*)d_in[13];
    const float* w2_wsb = (const float*)d_in[14];
    const float* w2_wv  = (const float*)d_in[15];
    const float* w2_wsv = (const float*)d_in[16];
    const float* w2_wsvb= (const float*)d_in[17];
    const float* w3_wh  = (const float*)d_in[18];
    const float* w3_ws  = (const float*)d_in[19];
    const float* w3_wsb = (const float*)d_in[20];
    const float* w3_wv  = (const float*)d_in[21];
    const float* w3_wsv = (const float*)d_in[22];
    const float* w3_wsvb= (const float*)d_in[23];

    int N = in_sizes[0] / 128;
    int E = in_sizes[3] / 32;
    float* out = (float*)d_out;

    // 4 launches per call: prep, edge, fin_s, fin_v
    prep_kernel<<<N, 128>>>(node_s, node_v, w1_wh, w1_ws);

    cudaFuncSetAttribute(edge_kernel,
                         cudaFuncAttributeMaxDynamicSharedMemorySize, SMEM_BYTES);
    edge_kernel<<<444, 128, SMEM_BYTES>>>(
        ei, edge_s, edge_v,
        w1_wh, w1_ws, w1_wsb, w1_wv, w1_wsv, w1_wsvb,
        w2_wh, w2_ws, w2_wsb, w2_wv, w2_wsv, w2_wsvb,
        w3_wh, w3_ws, w3_wsb, w3_wv, w3_wsv, w3_wsvb,
        E);

    finalize_s_kernel<<<(N * 64 + 255) / 256, 256>>>(mask, out, N);
    finalize_v_kernel<<<(N * 4 + 255) / 256, 256>>>(mask, out, N);
}